// round 7
// baseline (speedup 1.0000x reference)
#include <cuda_runtime.h>

// Problem constants (shapes fixed by dataset; code stays correct for any
// batch_list via the offsets kernel + generic path).
#define D_DIM   300          // embedding dim
#define DC      20           // columns per chunk (multiple of 4, divides 300)
#define DC4     (DC / 4)     // 5 float4 per row-chunk
#define NCHUNK  (D_DIM / DC) // 15
#define TR      256          // row tile (== nodes per graph in this dataset)
#define RB      32           // row-blocks
#define NT      (RB * DC4)   // 160 threads per CTA
#define KIT     (TR / RB)    // 8 rows per thread in fast path
#define MAXB    8192
#define EPSV    1e-12f

// Scratch (no cudaMalloc allowed): per-graph row offsets + actual graph count.
__device__ int g_off[MAXB + 1];
__device__ int g_B;

// ---------------------------------------------------------------------------
// Offsets kernel: detects int32 vs int64 batch_list layout. Fast path: if all
// counts are equal (dataset case), writes offsets arithmetically with no scan.
// Fallback: block-wide inclusive scan.
// ---------------------------------------------------------------------------
__global__ void offsets_kernel(const int* __restrict__ p32, int nb, int ntot) {
    __shared__ int sh[1024];
    __shared__ int s_stride, s_carry, s_uni, s_val;
    const int tid = threadIdx.x;

    if (tid == 0) {
        int stride = 1;
        if (nb > 1) {
            int v0 = p32[0], v1 = p32[1];
            if (v1 == 0 && v0 != 0) stride = 2;   // int64 little-endian
        }
        s_stride = stride;
        s_carry = 0;
        s_uni = 1;
        s_val = p32[0];
        g_off[0] = 0;
    }
    __syncthreads();

    const int st = s_stride;
    int B = nb;
    if (B > MAXB) B = MAXB;
    const int B1 = (st == 2) ? (B >> 1) : B;
    const int v0 = s_val;

    int uni = 1;
    for (int i = tid; i < B1; i += 1024)
        if (p32[(size_t)i * st] != v0) uni = 0;
    if (!uni) atomicAnd(&s_uni, 0);
    __syncthreads();

    if (s_uni && (long long)B1 * v0 == ntot) {
        for (int i = tid; i < B1; i += 1024)
            g_off[i + 1] = (i + 1) * v0;
        if (tid == 0) g_B = B1;
        return;
    }

    for (int base = 0; base < B1; base += 1024) {
        int i = base + tid;
        int v = (i < B1) ? p32[(size_t)i * st] : 0;
        sh[tid] = v;
        __syncthreads();
        #pragma unroll
        for (int o = 1; o < 1024; o <<= 1) {
            int t = (tid >= o) ? sh[tid - o] : 0;
            __syncthreads();
            sh[tid] += t;
            __syncthreads();
        }
        if (i < B1) g_off[i + 1] = s_carry + sh[tid];
        __syncthreads();
        if (tid == 0) s_carry += sh[1023];
        __syncthreads();
    }

    int Bfinal = B1;
    if (st == 2 && B1 > 0 && g_off[B1] != ntot && B > B1) {
        for (int base = B1; base < B; base += 1024) {
            int i = base + tid;
            int v = (i < B) ? p32[(size_t)i * st] : 0;
            sh[tid] = v;
            __syncthreads();
            #pragma unroll
            for (int o = 1; o < 1024; o <<= 1) {
                int t = (tid >= o) ? sh[tid - o] : 0;
                __syncthreads();
                sh[tid] += t;
                __syncthreads();
            }
            if (i < B) g_off[i + 1] = s_carry + sh[tid];
            __syncthreads();
            if (tid == 0) s_carry += sh[1023];
            __syncthreads();
        }
        Bfinal = B;
    }
    if (tid == 0) g_B = Bfinal;
}

// ---------------------------------------------------------------------------
// Helpers
// ---------------------------------------------------------------------------
__device__ __forceinline__ float4 min4(float4 a, float4 b) {
    return make_float4(fminf(a.x, b.x), fminf(a.y, b.y),
                       fminf(a.z, b.z), fminf(a.w, b.w));
}
__device__ __forceinline__ float4 max4(float4 a, float4 b) {
    return make_float4(fmaxf(a.x, b.x), fmaxf(a.y, b.y),
                       fmaxf(a.z, b.z), fmaxf(a.w, b.w));
}

// ---------------------------------------------------------------------------
// Main kernel: persistent CTAs (4/SM), 160 threads, one (graph, 20-col chunk)
// tile per loop iteration. Software-pipelined: tile T+1's 8 float4 loads are
// issued into a second register buffer BEFORE tile T's fold barriers, so DRAM
// reads stay in flight through the barrier/fold/store back-half. Single DRAM
// read + single DRAM write of the tensor.
// ---------------------------------------------------------------------------
__global__ void __launch_bounds__(NT, 4)
cube_norm_kernel(const float* __restrict__ x, float* __restrict__ y,
                 int ntiles) {
    __shared__ float pmn_s[RB * DC];   // 2560 B
    __shared__ float pmx_s[RB * DC];   // 2560 B
    __shared__ float smid[DC];
    __shared__ float sinv[DC];

    const int tid = threadIdx.x;
    const int j   = tid % DC4;         // column quad 0..4
    const int rb  = tid / DC4;         // row block 0..31
    const int B   = g_B;
    const int stride = gridDim.x;
    const size_t toff = (size_t)rb * D_DIM + 4 * j;  // thread offset in tile

    // ---- prologue: state for first tile ----
    int t = blockIdx.x;
    bool fast = false;
    int nr_cur = 0;
    size_t off = 0;
    float4 v[KIT];
    if (t < ntiles) {
        int g = t / NCHUNK;
        if (g >= B) return;
        int r0 = g_off[g];
        nr_cur = g_off[g + 1] - r0;
        off = (size_t)r0 * D_DIM + (t - g * NCHUNK) * DC + toff;
        fast = (nr_cur == TR);
        if (fast) {
            const float* p = x + off;
            #pragma unroll
            for (int k = 0; k < KIT; k++)
                v[k] = __ldcs((const float4*)(p + (size_t)k * RB * D_DIM));
        }
    }

    while (t < ntiles) {
        // ---- compute next tile's state; issue its loads early ----
        int tn = t + stride;
        bool nfast = false;
        int nnr = 0;
        size_t noff = 0;
        if (tn < ntiles) {
            int gn = tn / NCHUNK;
            if (gn >= B) {
                tn = ntiles;                      // uniform exit next iter
            } else {
                int r0n = g_off[gn];
                nnr = g_off[gn + 1] - r0n;
                noff = (size_t)r0n * D_DIM + (tn - gn * NCHUNK) * DC + toff;
                nfast = (nnr == TR);
            }
        }
        float4 w[KIT];
        if (nfast) {
            const float* pn = x + noff;
            #pragma unroll
            for (int k = 0; k < KIT; k++)
                w[k] = __ldcs((const float4*)(pn + (size_t)k * RB * D_DIM));
        }

        if (fast) {
            // ---- reduce current tile from registers ----
            float4 mn = v[0], mx = v[0];
            #pragma unroll
            for (int k = 1; k < KIT; k++) {
                mn = min4(mn, v[k]);
                mx = max4(mx, v[k]);
            }
            *(float4*)&pmn_s[rb * DC + 4 * j] = mn;
            *(float4*)&pmx_s[rb * DC + 4 * j] = mx;
            __syncthreads();

            if (tid < DC) {
                float fmn = pmn_s[tid];
                float fmx = pmx_s[tid];
                #pragma unroll
                for (int r = 1; r < RB; r++) {
                    fmn = fminf(fmn, pmn_s[r * DC + tid]);
                    fmx = fmaxf(fmx, pmx_s[r * DC + tid]);
                }
                smid[tid] = (fmx + fmn) * 0.5f;
                sinv[tid] = 1.0f / fmaxf((fmx - fmn) * 0.5f, EPSV);
            }
            __syncthreads();

            const float4 mid = *(const float4*)&smid[4 * j];
            const float4 inv = *(const float4*)&sinv[4 * j];

            float* q = y + off;
            #pragma unroll
            for (int k = 0; k < KIT; k++) {
                float4 o;
                o.x = (v[k].x - mid.x) * inv.x;
                o.y = (v[k].y - mid.y) * inv.y;
                o.z = (v[k].z - mid.z) * inv.z;
                o.w = (v[k].w - mid.w) * inv.w;
                __stcs((float4*)(q + (size_t)k * RB * D_DIM), o);
            }
        } else if (nr_cur > 0) {
            // ---------------- generic path (not hit by dataset) ------------
            const float* xg = x + off;
            float*       yg = y + off;
            float4 mn = make_float4( 3.402823466e38f,  3.402823466e38f,
                                     3.402823466e38f,  3.402823466e38f);
            float4 mx = make_float4(-3.402823466e38f, -3.402823466e38f,
                                    -3.402823466e38f, -3.402823466e38f);
            for (int r = rb; r < nr_cur; r += RB) {
                float4 a = *(const float4*)(xg + (size_t)(r - rb) * D_DIM);
                mn = min4(mn, a);
                mx = max4(mx, a);
            }
            *(float4*)&pmn_s[rb * DC + 4 * j] = mn;
            *(float4*)&pmx_s[rb * DC + 4 * j] = mx;
            __syncthreads();
            if (tid < DC) {
                float fmn = pmn_s[tid];
                float fmx = pmx_s[tid];
                #pragma unroll
                for (int r = 1; r < RB; r++) {
                    fmn = fminf(fmn, pmn_s[r * DC + tid]);
                    fmx = fmaxf(fmx, pmx_s[r * DC + tid]);
                }
                smid[tid] = (fmx + fmn) * 0.5f;
                sinv[tid] = 1.0f / fmaxf((fmx - fmn) * 0.5f, EPSV);
            }
            __syncthreads();
            const float4 mid = *(const float4*)&smid[4 * j];
            const float4 inv = *(const float4*)&sinv[4 * j];
            for (int r = rb; r < nr_cur; r += RB) {
                float4 a = *(const float4*)(xg + (size_t)(r - rb) * D_DIM);
                float4 o;
                o.x = (a.x - mid.x) * inv.x;
                o.y = (a.y - mid.y) * inv.y;
                o.z = (a.z - mid.z) * inv.z;
                o.w = (a.w - mid.w) * inv.w;
                *(float4*)(yg + (size_t)(r - rb) * D_DIM) = o;
            }
            __syncthreads();   // protect smem across iterations
        }

        // ---- advance pipeline ----
        if (nfast) {
            #pragma unroll
            for (int k = 0; k < KIT; k++) v[k] = w[k];
        }
        fast   = nfast;
        nr_cur = nnr;
        off    = noff;
        t      = tn;
    }
}

// ---------------------------------------------------------------------------
extern "C" void kernel_launch(void* const* d_in, const int* in_sizes, int n_in,
                              void* d_out, int out_size) {
    const float* x  = (const float*)d_in[0];
    const int*   bl = (const int*)d_in[1];
    float*       y  = (float*)d_out;

    const int nb   = in_sizes[1];
    const int ntot = in_sizes[0] / D_DIM;

    offsets_kernel<<<1, 1024>>>(bl, nb, ntot);

    int nbc = nb < MAXB ? nb : MAXB;
    if (nbc < 1) nbc = 1;
    const int ntiles = NCHUNK * nbc;

    int sms = 148;
    cudaDeviceGetAttribute(&sms, cudaDevAttrMultiProcessorCount, 0);
    int grid = 4 * sms;                   // persistent: 4 CTAs per SM
    if (grid > ntiles) grid = ntiles;

    cube_norm_kernel<<<grid, NT>>>(x, y, ntiles);
}